// round 16
// baseline (speedup 1.0000x reference)
#include <cuda_runtime.h>
#include <cuda_fp16.h>
#include <cstdint>

#define D_DIM  448
#define MTOT   32768
#define BM     128
#define BN     112
#define BK     64
#define ASB    160                         // A smem row stride in BYTES (fp16, v2 conflict-free)
#define BSB    160                         // B smem row stride in BYTES
#define A_STAGE_BYTES (BM * ASB)           // 20480
#define B_STAGE_BYTES (BN * BSB)           // 17920
#define STG_BYTES (A_STAGE_BYTES + B_STAGE_BYTES)   // 38400
#define SMEM_BYTES (2 * STG_BYTES)         // 76800 -> 2 CTAs/SM
#define PREP_GRID 296

// k16-interleave p(j)=4*((j&7)>>1)+2*(j>>3)+(j&1): one 8B load at half-offset
// 4t yields {k0+2t,2t+1} (low 4B) and {k0+2t+8,2t+9} (high 4B) — exactly the
// mma.m16n8k16 per-thread fragment pairs for both A and B.
__device__ __align__(16) __half g_Wh[D_DIM * D_DIM];   // W_eff^T [n][k_perm]
__device__ __align__(16) __half g_Xh[(size_t)MTOT * D_DIM];  // x [m][k_perm]

// ---- helpers ----------------------------------------------------------------
__device__ __forceinline__ uint32_t smem_u32(const void* p) {
    uint32_t a;
    asm("{ .reg .u64 t; cvta.to.shared.u64 t, %1; cvt.u32.u64 %0, t; }" : "=r"(a) : "l"(p));
    return a;
}
__device__ __forceinline__ void mma_f16(float* c, const uint32_t* a, uint32_t b0, uint32_t b1) {
    asm volatile(
        "mma.sync.aligned.m16n8k16.row.col.f32.f16.f16.f32 "
        "{%0,%1,%2,%3}, {%4,%5,%6,%7}, {%8,%9}, {%0,%1,%2,%3};"
        : "+f"(c[0]), "+f"(c[1]), "+f"(c[2]), "+f"(c[3])
        : "r"(a[0]), "r"(a[1]), "r"(a[2]), "r"(a[3]), "r"(b0), "r"(b1));
}
#define CP16(dst, src) \
    asm volatile("cp.async.cg.shared.global [%0], [%1], 16;" :: "r"(dst), "l"(src) : "memory")
#define CP_COMMIT() asm volatile("cp.async.commit_group;" ::: "memory")
#define CP_WAIT0()  asm volatile("cp.async.wait_group 0;" ::: "memory")

__device__ __forceinline__ int kperm16(int j) {   // j in [0,16)
    return 4 * ((j & 7) >> 1) + 2 * (j >> 3) + (j & 1);
}

// ---------------------------------------------------------------------------
// Prep kernel, grid 296 x 256:
//  part 1 (blocks 0..195): W_eff = (Wq*dA + Wk*dB + Wv*dC) @ Wo -> g_Wh
//     (32x32 tiles, 1-deep register prefetch — R13's measured-best form)
//  part 2 (all blocks):   grid-stride convert x -> g_Xh (fp16, k16-interleave)
// ---------------------------------------------------------------------------
__global__ void __launch_bounds__(256) prep_kernel(const float* __restrict__ x,
                                                   const float* __restrict__ Wq,
                                                   const float* __restrict__ Wk,
                                                   const float* __restrict__ Wv,
                                                   const float* __restrict__ Wo,
                                                   const float* __restrict__ A,
                                                   const float* __restrict__ Bm,
                                                   const float* __restrict__ C) {
    __shared__ float dg[3][D_DIM];
    __shared__ float Ms[32][33];
    __shared__ float Ws[32][33];
    const int tid = threadIdx.x;
    const int bid = blockIdx.x;

    if (bid < 196) {
        for (int i = tid; i < D_DIM; i += 256) {
            dg[0][i] = A[(size_t)i * D_DIM + i];
            dg[1][i] = Bm[(size_t)i * D_DIM + i];
            dg[2][i] = C[(size_t)i * D_DIM + i];
        }

        const int ty = tid >> 4, tx = tid & 15;
        const int by = bid / 14, bx = bid - by * 14;
        const int k0 = by * 32, n0 = bx * 32;
        const int lrow = tid >> 3;
        const int lc4  = (tid & 7) * 4;

        const size_t qoff = (size_t)(k0 + lrow) * D_DIM + lc4;
        const size_t ooff = (size_t)lrow * D_DIM + n0 + lc4;

        float4 pq = *reinterpret_cast<const float4*>(Wq + qoff);
        float4 pk = *reinterpret_cast<const float4*>(Wk + qoff);
        float4 pv = *reinterpret_cast<const float4*>(Wv + qoff);
        float4 po = *reinterpret_cast<const float4*>(Wo + ooff);
        __syncthreads();

        float acc[2][2] = {};
        for (int kt = 0; kt < D_DIM; kt += 32) {
            {
                const float4 da = *reinterpret_cast<const float4*>(&dg[0][kt + lc4]);
                const float4 db = *reinterpret_cast<const float4*>(&dg[1][kt + lc4]);
                const float4 dc = *reinterpret_cast<const float4*>(&dg[2][kt + lc4]);
                Ms[lrow][lc4 + 0] = pq.x * da.x + pk.x * db.x + pv.x * dc.x;
                Ms[lrow][lc4 + 1] = pq.y * da.y + pk.y * db.y + pv.y * dc.y;
                Ms[lrow][lc4 + 2] = pq.z * da.z + pk.z * db.z + pv.z * dc.z;
                Ms[lrow][lc4 + 3] = pq.w * da.w + pk.w * db.w + pv.w * dc.w;
                Ws[lrow][lc4 + 0] = po.x; Ws[lrow][lc4 + 1] = po.y;
                Ws[lrow][lc4 + 2] = po.z; Ws[lrow][lc4 + 3] = po.w;
            }
            __syncthreads();
            if (kt + 32 < D_DIM) {
                pq = *reinterpret_cast<const float4*>(Wq + qoff + kt + 32);
                pk = *reinterpret_cast<const float4*>(Wk + qoff + kt + 32);
                pv = *reinterpret_cast<const float4*>(Wv + qoff + kt + 32);
                po = *reinterpret_cast<const float4*>(Wo + ooff + (size_t)(kt + 32) * D_DIM);
            }
#pragma unroll
            for (int kk = 0; kk < 32; kk++) {
                const float a0 = Ms[ty][kk],      a1 = Ms[ty + 16][kk];
                const float b0 = Ws[kk][tx],      b1 = Ws[kk][tx + 16];
                acc[0][0] += a0 * b0; acc[0][1] += a0 * b1;
                acc[1][0] += a1 * b0; acc[1][1] += a1 * b1;
            }
            __syncthreads();
        }
#pragma unroll
        for (int i = 0; i < 2; i++) {
            const int k = k0 + ty + i * 16;
            const int kp = (k & ~15) | kperm16(k & 15);
#pragma unroll
            for (int jj = 0; jj < 2; jj++) {
                const int n = n0 + tx + jj * 16;
                g_Wh[(size_t)n * D_DIM + kp] = __float2half_rn(acc[i][jj]);
            }
        }
    }

    // ---- part 2: convert x -> g_Xh (all blocks, grid-stride over k16 units)
    {
        const int NUNITS = MTOT * (D_DIM / 16);     // 917504
        const int stride = PREP_GRID * 256;
        for (int u = bid * 256 + tid; u < NUNITS; u += stride) {
            const int m   = u / (D_DIM / 16);
            const int c16 = u - m * (D_DIM / 16);
            const float* src = x + (size_t)m * D_DIM + c16 * 16;
            float f[16];
#pragma unroll
            for (int j = 0; j < 4; j++)
                *reinterpret_cast<float4*>(f + 4 * j) =
                    *reinterpret_cast<const float4*>(src + 4 * j);
            __half h[16];
#pragma unroll
            for (int j = 0; j < 16; j++)
                h[kperm16(j)] = __float2half_rn(f[j]);
            uint4* dst = reinterpret_cast<uint4*>(g_Xh + (size_t)m * D_DIM + c16 * 16);
            dst[0] = reinterpret_cast<const uint4*>(h)[0];
            dst[1] = reinterpret_cast<const uint4*>(h)[1];
        }
    }
}

// ---------------------------------------------------------------------------
// Main GEMM: out = x @ W_eff via fp16 mma.sync m16n8k16 (fp32 accum).
// BM=128, BN=112, BK=64, 7 iterations, NSTG=2 double buffer, 256 threads
// (8 warps 4m x 2n), warp tile 32x56. BOTH operands fp16 in smem, k16-
// interleaved: every fragment pair is one LDS.64, zero in-loop converts.
// ---------------------------------------------------------------------------
__global__ void __launch_bounds__(256, 2) gemm_f16_kernel(float* __restrict__ out) {
    extern __shared__ __align__(16) char smem[];

    const int tid   = threadIdx.x;
    const int wid   = tid >> 5;
    const int lane  = tid & 31;
    const int g     = lane >> 2;
    const int t     = lane & 3;
    const int warpM = wid & 3;
    const int warpN = wid >> 2;

    const int m0 = blockIdx.y * BM;
    const int n0 = blockIdx.x * BN;

    const uint32_t smem_base = smem_u32(smem);

    float acc[2][7][4];
#pragma unroll
    for (int i = 0; i < 2; i++)
#pragma unroll
        for (int j = 0; j < 7; j++)
#pragma unroll
            for (int q = 0; q < 4; q++) acc[i][j][q] = 0.f;

    auto load_stage = [&](int s, int kt) {
        const uint32_t aBase = smem_base + (uint32_t)(s * STG_BYTES);
        const uint32_t bBase = aBase + (uint32_t)A_STAGE_BYTES;
        // A: 128 rows x 128B = 1024 16B chunks, 4 per thread
#pragma unroll
        for (int j = 0; j < 4; j++) {
            const int id  = tid + j * 256;
            const int row = id >> 3;
            const int c   = id & 7;
            CP16(aBase + (uint32_t)(row * ASB + c * 16),
                 (const char*)g_Xh + ((size_t)(m0 + row) * D_DIM + kt) * 2 + c * 16);
        }
        // B: 112 rows x 128B = 896 chunks, 3 per thread + 128 extra
#pragma unroll
        for (int j = 0; j < 3; j++) {
            const int id  = tid + j * 256;
            const int row = id >> 3;
            const int c   = id & 7;
            CP16(bBase + (uint32_t)(row * BSB + c * 16),
                 (const char*)g_Wh + ((size_t)(n0 + row) * D_DIM + kt) * 2 + c * 16);
        }
        if (tid < 128) {
            const int id  = tid + 768;
            const int row = id >> 3;
            const int c   = id & 7;
            CP16(bBase + (uint32_t)(row * BSB + c * 16),
                 (const char*)g_Wh + ((size_t)(n0 + row) * D_DIM + kt) * 2 + c * 16);
        }
    };

    load_stage(0, 0);
    CP_COMMIT();

    const int NIT = D_DIM / BK;   // 7
#pragma unroll 1
    for (int it = 0; it < NIT; it++) {
        CP_WAIT0();
        __syncthreads();

        if (it + 1 < NIT) load_stage((it + 1) & 1, (it + 1) * BK);
        CP_COMMIT();

        const char* stage = smem + (it & 1) * STG_BYTES;
        const char* Arow  = stage + (warpM * 32 + g) * ASB;
        const char* Brow  = stage + A_STAGE_BYTES + (warpN * 56 + g) * BSB;

#pragma unroll
        for (int kk2 = 0; kk2 < 4; kk2++) {    // four k16 blocks per BK=64
            uint32_t af[2][4];
#pragma unroll
            for (int mi = 0; mi < 2; mi++) {
                // row g: {2t,2t+1 | 2t+8,2t+9}; row g+8: same
                const uint2 a0 = *reinterpret_cast<const uint2*>(
                    Arow + mi * (16 * ASB) + kk2 * 32 + 8 * t);
                const uint2 a1 = *reinterpret_cast<const uint2*>(
                    Arow + mi * (16 * ASB) + 8 * ASB + kk2 * 32 + 8 * t);
                af[mi][0] = a0.x; af[mi][2] = a0.y;
                af[mi][1] = a1.x; af[mi][3] = a1.y;
            }
#pragma unroll
            for (int ni = 0; ni < 7; ni++) {
                const uint2 bv = *reinterpret_cast<const uint2*>(
                    Brow + ni * 8 * BSB + kk2 * 32 + 8 * t);
                mma_f16(acc[0][ni], af[0], bv.x, bv.y);
                mma_f16(acc[1][ni], af[1], bv.x, bv.y);
            }
        }
    }

    // ---- epilogue: rows (g, g+8), cols (2t, 2t+1) per (mi, ni)
#pragma unroll
    for (int mi = 0; mi < 2; mi++) {
        const int r0 = m0 + warpM * 32 + mi * 16 + g;
#pragma unroll
        for (int ni = 0; ni < 7; ni++) {
            const int c0 = n0 + warpN * 56 + ni * 8 + 2 * t;
            float2 v0, v1;
            v0.x = acc[mi][ni][0]; v0.y = acc[mi][ni][1];
            v1.x = acc[mi][ni][2]; v1.y = acc[mi][ni][3];
            *reinterpret_cast<float2*>(out + (size_t)r0 * D_DIM + c0)       = v0;
            *reinterpret_cast<float2*>(out + (size_t)(r0 + 8) * D_DIM + c0) = v1;
        }
    }
}

// ---------------------------------------------------------------------------
extern "C" void kernel_launch(void* const* d_in, const int* in_sizes, int n_in,
                              void* d_out, int out_size) {
    const float* x  = (const float*)d_in[0];
    const float* Wq = (const float*)d_in[1];
    const float* Wk = (const float*)d_in[2];
    const float* Wv = (const float*)d_in[3];
    const float* Wo = (const float*)d_in[4];
    const float* A  = (const float*)d_in[5];
    const float* B  = (const float*)d_in[6];
    const float* C  = (const float*)d_in[7];

    cudaFuncSetAttribute(gemm_f16_kernel, cudaFuncAttributeMaxDynamicSharedMemorySize,
                         SMEM_BYTES);

    prep_kernel<<<PREP_GRID, 256>>>(x, Wq, Wk, Wv, Wo, A, B, C);
    gemm_f16_kernel<<<dim3(D_DIM / BN, MTOT / BM), 256, SMEM_BYTES>>>((float*)d_out);
}

// round 17
// speedup vs baseline: 1.0218x; 1.0218x over previous
#include <cuda_runtime.h>
#include <cuda_fp16.h>
#include <cstdint>

#define D_DIM  448
#define MTOT   32768
#define BM     128
#define BN     112
#define BK     64
#define NSTG   3
#define ASB    160                         // A smem row stride in BYTES (fp16, v2 conflict-free)
#define BSB    160                         // B smem row stride in BYTES
#define A_STAGE_BYTES (BM * ASB)           // 20480
#define B_STAGE_BYTES (BN * BSB)           // 17920
#define STG_BYTES (A_STAGE_BYTES + B_STAGE_BYTES)   // 38400
#define SMEM_BYTES (NSTG * STG_BYTES)      // 115200; 2 CTAs/SM = 230400 <= 233472
#define PREP_GRID 296

// k16-interleave p(j)=4*((j&7)>>1)+2*(j>>3)+(j&1): one 8B load at half-offset
// 4t yields {k0+2t,2t+1} (low 4B) and {k0+2t+8,2t+9} (high 4B) — exactly the
// mma.m16n8k16 per-thread fragment pairs for both A and B.
__device__ __align__(16) __half g_Wh[D_DIM * D_DIM];          // W_eff^T [n][k_perm]
__device__ __align__(16) __half g_Xh[(size_t)MTOT * D_DIM];   // x [m][k_perm]

// ---- helpers ----------------------------------------------------------------
__device__ __forceinline__ uint32_t smem_u32(const void* p) {
    uint32_t a;
    asm("{ .reg .u64 t; cvta.to.shared.u64 t, %1; cvt.u32.u64 %0, t; }" : "=r"(a) : "l"(p));
    return a;
}
__device__ __forceinline__ void mma_f16(float* c, const uint32_t* a, uint32_t b0, uint32_t b1) {
    asm volatile(
        "mma.sync.aligned.m16n8k16.row.col.f32.f16.f16.f32 "
        "{%0,%1,%2,%3}, {%4,%5,%6,%7}, {%8,%9}, {%0,%1,%2,%3};"
        : "+f"(c[0]), "+f"(c[1]), "+f"(c[2]), "+f"(c[3])
        : "r"(a[0]), "r"(a[1]), "r"(a[2]), "r"(a[3]), "r"(b0), "r"(b1));
}
#define CP16(dst, src) \
    asm volatile("cp.async.cg.shared.global [%0], [%1], 16;" :: "r"(dst), "l"(src) : "memory")
#define CP_COMMIT() asm volatile("cp.async.commit_group;" ::: "memory")
#define CP_WAIT1()  asm volatile("cp.async.wait_group 1;" ::: "memory")

__device__ __forceinline__ int kperm16(int j) {   // j in [0,16)
    return 4 * ((j & 7) >> 1) + 2 * (j >> 3) + (j & 1);
}

// ---------------------------------------------------------------------------
// Prep kernel, grid 296 x 256 (R16, measured):
//  blocks 0..195: W_eff tile -> g_Wh (fp16, k16-interleaved), then join convert
//  blocks 196+ :  convert x -> g_Xh immediately (weff and convert overlap)
// ---------------------------------------------------------------------------
__global__ void __launch_bounds__(256) prep_kernel(const float* __restrict__ x,
                                                   const float* __restrict__ Wq,
                                                   const float* __restrict__ Wk,
                                                   const float* __restrict__ Wv,
                                                   const float* __restrict__ Wo,
                                                   const float* __restrict__ A,
                                                   const float* __restrict__ Bm,
                                                   const float* __restrict__ C) {
    __shared__ float dg[3][D_DIM];
    __shared__ float Ms[32][33];
    __shared__ float Ws[32][33];
    const int tid = threadIdx.x;
    const int bid = blockIdx.x;

    if (bid < 196) {
        for (int i = tid; i < D_DIM; i += 256) {
            dg[0][i] = A[(size_t)i * D_DIM + i];
            dg[1][i] = Bm[(size_t)i * D_DIM + i];
            dg[2][i] = C[(size_t)i * D_DIM + i];
        }

        const int ty = tid >> 4, tx = tid & 15;
        const int by = bid / 14, bx = bid - by * 14;
        const int k0 = by * 32, n0 = bx * 32;
        const int lrow = tid >> 3;
        const int lc4  = (tid & 7) * 4;

        const size_t qoff = (size_t)(k0 + lrow) * D_DIM + lc4;
        const size_t ooff = (size_t)lrow * D_DIM + n0 + lc4;

        float4 pq = *reinterpret_cast<const float4*>(Wq + qoff);
        float4 pk = *reinterpret_cast<const float4*>(Wk + qoff);
        float4 pv = *reinterpret_cast<const float4*>(Wv + qoff);
        float4 po = *reinterpret_cast<const float4*>(Wo + ooff);
        __syncthreads();

        float acc[2][2] = {};
        for (int kt = 0; kt < D_DIM; kt += 32) {
            {
                const float4 da = *reinterpret_cast<const float4*>(&dg[0][kt + lc4]);
                const float4 db = *reinterpret_cast<const float4*>(&dg[1][kt + lc4]);
                const float4 dc = *reinterpret_cast<const float4*>(&dg[2][kt + lc4]);
                Ms[lrow][lc4 + 0] = pq.x * da.x + pk.x * db.x + pv.x * dc.x;
                Ms[lrow][lc4 + 1] = pq.y * da.y + pk.y * db.y + pv.y * dc.y;
                Ms[lrow][lc4 + 2] = pq.z * da.z + pk.z * db.z + pv.z * dc.z;
                Ms[lrow][lc4 + 3] = pq.w * da.w + pk.w * db.w + pv.w * dc.w;
                Ws[lrow][lc4 + 0] = po.x; Ws[lrow][lc4 + 1] = po.y;
                Ws[lrow][lc4 + 2] = po.z; Ws[lrow][lc4 + 3] = po.w;
            }
            __syncthreads();
            if (kt + 32 < D_DIM) {
                pq = *reinterpret_cast<const float4*>(Wq + qoff + kt + 32);
                pk = *reinterpret_cast<const float4*>(Wk + qoff + kt + 32);
                pv = *reinterpret_cast<const float4*>(Wv + qoff + kt + 32);
                po = *reinterpret_cast<const float4*>(Wo + ooff + (size_t)(kt + 32) * D_DIM);
            }
#pragma unroll
            for (int kk = 0; kk < 32; kk++) {
                const float a0 = Ms[ty][kk],      a1 = Ms[ty + 16][kk];
                const float b0 = Ws[kk][tx],      b1 = Ws[kk][tx + 16];
                acc[0][0] += a0 * b0; acc[0][1] += a0 * b1;
                acc[1][0] += a1 * b0; acc[1][1] += a1 * b1;
            }
            __syncthreads();
        }
#pragma unroll
        for (int i = 0; i < 2; i++) {
            const int k = k0 + ty + i * 16;
            const int kp = (k & ~15) | kperm16(k & 15);
#pragma unroll
            for (int jj = 0; jj < 2; jj++) {
                const int n = n0 + tx + jj * 16;
                g_Wh[(size_t)n * D_DIM + kp] = __float2half_rn(acc[i][jj]);
            }
        }
    }

    // ---- convert x -> g_Xh (all blocks; grid-stride over k16 units)
    {
        const int NUNITS = MTOT * (D_DIM / 16);     // 917504
        const int stride = PREP_GRID * 256;
        for (int u = bid * 256 + tid; u < NUNITS; u += stride) {
            const int m   = u / (D_DIM / 16);
            const int c16 = u - m * (D_DIM / 16);
            const float* src = x + (size_t)m * D_DIM + c16 * 16;
            float f[16];
#pragma unroll
            for (int j = 0; j < 4; j++)
                *reinterpret_cast<float4*>(f + 4 * j) =
                    *reinterpret_cast<const float4*>(src + 4 * j);
            __half h[16];
#pragma unroll
            for (int j = 0; j < 16; j++)
                h[kperm16(j)] = __float2half_rn(f[j]);
            uint4* dst = reinterpret_cast<uint4*>(g_Xh + (size_t)m * D_DIM + c16 * 16);
            dst[0] = reinterpret_cast<const uint4*>(h)[0];
            dst[1] = reinterpret_cast<const uint4*>(h)[1];
        }
    }
}

// ---------------------------------------------------------------------------
// Main GEMM: out = x @ W_eff via fp16 mma.sync m16n8k16 (fp32 accum).
// BM=128, BN=112, BK=64, 7 iterations. NEW: NSTG=3, wait_group 1 -> load(it)
// issued at it-2: two compute blocks of cover, overlapping the per-iter L2
// transfer (~1800 cyc chip-wide) with compute instead of serializing.
// 256 threads (8 warps 4m x 2n), warp tile 32x56, both operands fp16/k16-
// interleaved in smem (every fragment pair = one LDS.64).
// ---------------------------------------------------------------------------
__global__ void __launch_bounds__(256, 2) gemm_f16_kernel(float* __restrict__ out) {
    extern __shared__ __align__(16) char smem[];

    const int tid   = threadIdx.x;
    const int wid   = tid >> 5;
    const int lane  = tid & 31;
    const int g     = lane >> 2;
    const int t     = lane & 3;
    const int warpM = wid & 3;
    const int warpN = wid >> 2;

    const int m0 = blockIdx.y * BM;
    const int n0 = blockIdx.x * BN;

    const uint32_t smem_base = smem_u32(smem);

    float acc[2][7][4];
#pragma unroll
    for (int i = 0; i < 2; i++)
#pragma unroll
        for (int j = 0; j < 7; j++)
#pragma unroll
            for (int q = 0; q < 4; q++) acc[i][j][q] = 0.f;

    auto load_stage = [&](int s, int kt) {
        const uint32_t aBase = smem_base + (uint32_t)(s * STG_BYTES);
        const uint32_t bBase = aBase + (uint32_t)A_STAGE_BYTES;
        // A: 128 rows x 128B = 1024 16B chunks, 4 per thread
#pragma unroll
        for (int j = 0; j < 4; j++) {
            const int id  = tid + j * 256;
            const int row = id >> 3;
            const int c   = id & 7;
            CP16(aBase + (uint32_t)(row * ASB + c * 16),
                 (const char*)g_Xh + ((size_t)(m0 + row) * D_DIM + kt) * 2 + c * 16);
        }
        // B: 112 rows x 128B = 896 chunks, 3 per thread + 128 extra
#pragma unroll
        for (int j = 0; j < 3; j++) {
            const int id  = tid + j * 256;
            const int row = id >> 3;
            const int c   = id & 7;
            CP16(bBase + (uint32_t)(row * BSB + c * 16),
                 (const char*)g_Wh + ((size_t)(n0 + row) * D_DIM + kt) * 2 + c * 16);
        }
        if (tid < 128) {
            const int id  = tid + 768;
            const int row = id >> 3;
            const int c   = id & 7;
            CP16(bBase + (uint32_t)(row * BSB + c * 16),
                 (const char*)g_Wh + ((size_t)(n0 + row) * D_DIM + kt) * 2 + c * 16);
        }
    };

    load_stage(0, 0);
    CP_COMMIT();
    load_stage(1, BK);
    CP_COMMIT();

    const int NIT = D_DIM / BK;   // 7
#pragma unroll 1
    for (int it = 0; it < NIT; it++) {
        CP_WAIT1();          // stage it resident; stage it+1 may still be in flight
        __syncthreads();     // all warps done with iter it-1 -> buffer (it+2)%3 free

        if (it + 2 < NIT) load_stage((it + 2) % NSTG, (it + 2) * BK);
        CP_COMMIT();         // unconditional: keeps group accounting exact

        const char* stage = smem + (it % NSTG) * STG_BYTES;
        const char* Arow  = stage + (warpM * 32 + g) * ASB;
        const char* Brow  = stage + A_STAGE_BYTES + (warpN * 56 + g) * BSB;

#pragma unroll
        for (int kk2 = 0; kk2 < 4; kk2++) {    // four k16 blocks per BK=64
            uint32_t af[2][4];
#pragma unroll
            for (int mi = 0; mi < 2; mi++) {
                const uint2 a0 = *reinterpret_cast<const uint2*>(
                    Arow + mi * (16 * ASB) + kk2 * 32 + 8 * t);
                const uint2 a1 = *reinterpret_cast<const uint2*>(
                    Arow + mi * (16 * ASB) + 8 * ASB + kk2 * 32 + 8 * t);
                af[mi][0] = a0.x; af[mi][2] = a0.y;
                af[mi][1] = a1.x; af[mi][3] = a1.y;
            }
#pragma unroll
            for (int ni = 0; ni < 7; ni++) {
                const uint2 bv = *reinterpret_cast<const uint2*>(
                    Brow + ni * 8 * BSB + kk2 * 32 + 8 * t);
                mma_f16(acc[0][ni], af[0], bv.x, bv.y);
                mma_f16(acc[1][ni], af[1], bv.x, bv.y);
            }
        }
    }

    // ---- epilogue: rows (g, g+8), cols (2t, 2t+1) per (mi, ni)
#pragma unroll
    for (int mi = 0; mi < 2; mi++) {
        const int r0 = m0 + warpM * 32 + mi * 16 + g;
#pragma unroll
        for (int ni = 0; ni < 7; ni++) {
            const int c0 = n0 + warpN * 56 + ni * 8 + 2 * t;
            float2 v0, v1;
            v0.x = acc[mi][ni][0]; v0.y = acc[mi][ni][1];
            v1.x = acc[mi][ni][2]; v1.y = acc[mi][ni][3];
            *reinterpret_cast<float2*>(out + (size_t)r0 * D_DIM + c0)       = v0;
            *reinterpret_cast<float2*>(out + (size_t)(r0 + 8) * D_DIM + c0) = v1;
        }
    }
}

// ---------------------------------------------------------------------------
extern "C" void kernel_launch(void* const* d_in, const int* in_sizes, int n_in,
                              void* d_out, int out_size) {
    const float* x  = (const float*)d_in[0];
    const float* Wq = (const float*)d_in[1];
    const float* Wk = (const float*)d_in[2];
    const float* Wv = (const float*)d_in[3];
    const float* Wo = (const float*)d_in[4];
    const float* A  = (const float*)d_in[5];
    const float* B  = (const float*)d_in[6];
    const float* C  = (const float*)d_in[7];

    cudaFuncSetAttribute(gemm_f16_kernel, cudaFuncAttributeMaxDynamicSharedMemorySize,
                         SMEM_BYTES);

    prep_kernel<<<PREP_GRID, 256>>>(x, Wq, Wk, Wv, Wo, A, B, C);
    gemm_f16_kernel<<<dim3(D_DIM / BN, MTOT / BM), 256, SMEM_BYTES>>>((float*)d_out);
}